// round 14
// baseline (speedup 1.0000x reference)
#include <cuda_runtime.h>
#include <cuda_fp16.h>
#include <math.h>
#include <stdint.h>

// ---------------- problem constants ----------------
#define B_ 8
#define H_ 192
#define W_ 192
#define h_ 96
#define w_ 96
#define R_ELEMS (B_*64*H_*W_)        // 18,874,368

// weight-chunk table (each chunk = 16KB: 8KB hi + 8KB lo, [n][k] swizzled fp16)
#define CH_UP 0      // 7x7, CG=2 -> 98 chunks
#define CH_C2 98     // 3x3, CG=1 -> 9
#define CH_D1 107    // 3x3, CG=2 -> 18
#define CH_D2 125    // 9
#define CH_D3 134    // 9
#define CH_TOTAL 143

// ---------------- scratch ----------------
__device__ __align__(16) unsigned char g_wbf[CH_TOTAL * 16384];
__device__ float g_u[B_*64*h_*w_];
__device__ float g_diffs[B_*h_*w_];
__device__ float g_smap[B_*H_*W_];
__device__ __align__(16) __half g_fn16[R_ELEMS];   // NHWC fp16
__device__ __align__(16) __half g_r116[R_ELEMS];   // NHWC fp16
__device__ __align__(16) __half g_r216[R_ELEMS];   // NHWC fp16

// ---------------- helpers ----------------
__device__ __forceinline__ uint32_t smem_u32(const void* p) {
    uint32_t a;
    asm("{ .reg .u64 t; cvta.to.shared.u64 t, %1; cvt.u32.u64 %0, t; }" : "=r"(a) : "l"(p));
    return a;
}
__device__ __forceinline__ void ldm4(uint32_t addr, uint32_t r[4]) {
    asm volatile("ldmatrix.sync.aligned.m8n8.x4.shared.b16 {%0,%1,%2,%3}, [%4];"
                 : "=r"(r[0]), "=r"(r[1]), "=r"(r[2]), "=r"(r[3]) : "r"(addr));
}
__device__ __forceinline__ void mma16816(float c[4], const uint32_t a[4],
                                         uint32_t b0, uint32_t b1) {
    asm volatile(
        "mma.sync.aligned.m16n8k16.row.col.f32.f16.f16.f32 "
        "{%0,%1,%2,%3}, {%4,%5,%6,%7}, {%8,%9}, {%0,%1,%2,%3};"
        : "+f"(c[0]), "+f"(c[1]), "+f"(c[2]), "+f"(c[3])
        : "r"(a[0]), "r"(a[1]), "r"(a[2]), "r"(a[3]), "r"(b0), "r"(b1));
}
__device__ __forceinline__ void cpa16(uint32_t saddr, const void* g) {
    asm volatile("cp.async.cg.shared.global [%0], [%1], 16;" :: "r"(saddr), "l"(g) : "memory");
}
__device__ __forceinline__ void cpa4(uint32_t saddr, const void* g) {
    asm volatile("cp.async.ca.shared.global [%0], [%1], 4;" :: "r"(saddr), "l"(g) : "memory");
}
#define CPA_COMMIT() asm volatile("cp.async.commit_group;" ::: "memory")
#define CPA_WAIT0()  asm volatile("cp.async.wait_group 0;" ::: "memory")

__device__ __forceinline__ float gelu_exact(float y) {
    return 0.5f * y * (1.0f + erff(y * 0.70710678118654752f));
}
__device__ __forceinline__ uint32_t packh2(float a, float b) {
    __half2 h = __floats2half2_rn(a, b);
    return *(uint32_t*)&h;
}
// bilinear sample, exact fp32 expression order of the original up2_kernel
__device__ __forceinline__ float bil96(const float* p, int iy0, int iy1, float wy,
                                       int ix0, int ix1, float wx) {
    float a = p[iy0 * 96 + ix0], b = p[iy1 * 96 + ix0];
    float c = p[iy0 * 96 + ix1], d = p[iy1 * 96 + ix1];
    float ra = a * (1.f - wy) + b * wy;
    float rb = c * (1.f - wy) + d * wy;
    return ra * (1.f - wx) + rb * wx;
}
// same expression, stride-20 smem patch
__device__ __forceinline__ float bil20(const float* p, int iy0, int iy1, float wy,
                                       int ix0, int ix1, float wx) {
    float a = p[iy0 * 20 + ix0], b = p[iy1 * 20 + ix0];
    float c = p[iy0 * 20 + ix1], d = p[iy1 * 20 + ix1];
    float ra = a * (1.f - wy) + b * wy;
    float rb = c * (1.f - wy) + d * wy;
    return ra * (1.f - wx) + rb * wx;
}

// ---------------- fused weight prep: all 5 conv weight sets ----------------
__global__ void prep_all(const float* __restrict__ W_up, const float* __restrict__ W_c2,
                         const float* __restrict__ W_d1, const float* __restrict__ W_d2,
                         const float* __restrict__ W_d3, unsigned char* __restrict__ dst)
{
    int total = CH_TOTAL * 4096;
    for (int idx = blockIdx.x * blockDim.x + threadIdx.x; idx < total;
         idx += gridDim.x * blockDim.x) {
        int chunk = idx >> 12;
        int e = idx & 4095;
        int n = e >> 6, k = e & 63;
        const float* W; int CIN, KK, local;
        if (chunk < 98)       { W = W_up; CIN = 128; KK = 49; local = chunk; }
        else if (chunk < 107) { W = W_c2; CIN = 64;  KK = 9;  local = chunk - 98; }
        else if (chunk < 125) { W = W_d1; CIN = 128; KK = 9;  local = chunk - 107; }
        else if (chunk < 134) { W = W_d2; CIN = 64;  KK = 9;  local = chunk - 125; }
        else                  { W = W_d3; CIN = 64;  KK = 9;  local = chunk - 134; }
        int CG = CIN >> 6;
        int tap = local / CG, cg = local - tap * CG;
        float w = W[((size_t)n * CIN + cg * 64 + k) * KK + tap];
        __half hb = __float2half_rn(w);
        __half lb = __float2half_rn(w - __half2float(hb));
        uint32_t off = (uint32_t)n * 128 + ((((k >> 3) ^ (n & 7))) << 4) + (k & 7) * 2;
        unsigned char* base = dst + (size_t)chunk * 16384;
        *(unsigned short*)(base + off)        = __half_as_ushort(hb);
        *(unsigned short*)(base + 8192 + off) = __half_as_ushort(lb);
    }
}

// ---------------- HMMA implicit-GEMM conv (group-staged weights) ----------------
// TM=8 rows x 32 px per CTA (M=256), 64 out chans; warp tile m64 x n32.
// AMODE 0: input = inA (fp32 NCHW).  AMODE 1: inA * aux(smap).
// AMODE 2: cg0 = bilinear-up2(aux = u), cg1 = inH (fp16 NHWC).
// AMODE 3: input = inH (fp16 NHWC).
// MODE 0: beta*(acc+bias)   MODE 1: gelu(bn(acc+bias))
// OUTF 0: fp32 NCHW (outF)  OUTF 1: fp16 NHWC (outH)
template<int KS, int CG, int G, int MODE, int AMODE, int OUTF>
__global__ __launch_bounds__(256, 2)
void tconv(const float* __restrict__ inA, const __half* __restrict__ inH,
           const float* __restrict__ aux,
           const uint4* __restrict__ wch, const float* __restrict__ bias,
           const float* __restrict__ gg, const float* __restrict__ bb,
           const float* __restrict__ mm, const float* __restrict__ vv,
           const float* __restrict__ betap,
           float* __restrict__ outF, __half* __restrict__ outH,
           int H, int W)
{
    constexpr int PAD = KS / 2;
    constexpr int TM  = 8;
    constexpr int IH  = TM + KS - 1;
    constexpr int IWP = (KS == 3) ? 34 : 40;
    constexpr int NPX = IH * IWP;
    constexpr int KK  = KS * KS;
    constexpr int GPC = (KK + G - 1) / G;
    constexpr int NGRP = GPC * CG;
    constexpr int OFF_A = 1024;
    constexpr int OFF_B = 1024 + NPX * 128;
    constexpr int BSTRIDE = G * 8192;

    extern __shared__ char smem_raw[];
    char* smem = (char*)(((uintptr_t)smem_raw + 1023) & ~(uintptr_t)1023);
    uint32_t sb = smem_u32(smem);
    float* epi = (float*)smem;

    int tid = threadIdx.x, wid = tid >> 5, lane = tid & 31;
    int x0 = blockIdx.x * 32, y0 = blockIdx.y * TM, b = blockIdx.z;
    size_t HW = (size_t)H * W;

    auto stage_group = [&](int fg, int buf) {
        int cgg = fg / GPC, grp = fg - cgg * GPC;
        int t0 = grp * G;
        int cnt = (KK - t0 < G) ? (KK - t0) : G;
        for (int j = 0; j < cnt; j++) {
            int chunk = (t0 + j) * CG + cgg;
            const uint4* srcB = wch + (size_t)chunk * 1024;
            uint32_t dstB = sb + OFF_B + buf * BSTRIDE + j * 8192;
#pragma unroll
            for (int k = 0; k < 2; k++)
                cpa16(dstB + (uint32_t)(tid + k * 256) * 16, srcB + tid + k * 256);
        }
        CPA_COMMIT();
    };

    stage_group(0, 0);

    if (tid < 64) {
        int c = tid;
        float s, t;
        if (MODE == 1) {
            s = gg[c] * rsqrtf(vv[c] + 1e-5f);
            t = (bias[c] - mm[c]) * s + bb[c];
        } else {
            float bt = *betap;
            s = bt; t = bt * bias[c];
        }
        epi[c] = s; epi[64 + c] = t;
    }

    float acc[16][4];
#pragma unroll
    for (int i = 0; i < 16; i++)
#pragma unroll
        for (int j = 0; j < 4; j++) acc[i][j] = 0.f;

    int wm = wid >> 1, nh = wid & 1;
    int ar = lane & 15, akq = lane >> 4;
    int br = lane & 15, bkq = lane >> 4;

    int fg = 0;
    for (int cg = 0; cg < CG; cg++) {
        __syncthreads();

        // ---- stage halo ----
        constexpr int TOT = NPX * 8;
        bool h16 = (AMODE == 3) || (AMODE == 2 && CG == 2);
        if (h16 && (AMODE == 3 || cg == 1)) {
            for (int item = tid; item < TOT; item += 256) {
                int ph = item >> 3, o = item & 7;
                int hy = ph / IWP, hx = ph - hy * IWP;
                int gy = y0 + hy - PAD;
                int gx = x0 + hx - PAD;
                uint4 val = make_uint4(0, 0, 0, 0);
                if ((unsigned)gy < (unsigned)H && (unsigned)gx < (unsigned)W)
                    val = *(const uint4*)(inH + ((((size_t)b * H + gy) * W + gx) << 6) + o * 8);
                uint32_t ad = (uint32_t)ph * 128 + (((o ^ (ph & 7))) << 4);
                *(uint4*)(smem + OFF_A + ad) = val;
            }
        } else {
            const float* src = nullptr;
            if (AMODE != 2) src = inA + ((size_t)b * (CG * 64) + cg * 64) * HW;
            const float rr = 95.f / 191.f;
            for (int item = tid; item < TOT; item += 256) {
                int o  = item / NPX;
                int ph = item - o * NPX;
                int hy = ph / IWP, hx = ph - hy * IWP;
                int gy = y0 + hy - PAD;
                int gx = x0 + hx - PAD;
                float v[8];
                bool inb = (unsigned)gy < (unsigned)H && (unsigned)gx < (unsigned)W;
                if (AMODE == 2) {
                    if (inb) {
                        float sy = gy * rr; int iy0 = (int)sy; float wy = sy - (float)iy0;
                        int iy1 = min(iy0 + 1, 95);
                        float sx = gx * rr; int ix0 = (int)sx; float wx = sx - (float)ix0;
                        int ix1 = min(ix0 + 1, 95);
                        const float* up = aux + (size_t)(b * 64 + o * 8) * 9216;
#pragma unroll
                        for (int j = 0; j < 8; j++)
                            v[j] = bil96(up + j * 9216, iy0, iy1, wy, ix0, ix1, wx);
                    } else {
#pragma unroll
                        for (int j = 0; j < 8; j++) v[j] = 0.f;
                    }
                } else {
                    if (inb) {
                        const float* p = src + (size_t)(o * 8) * HW + (size_t)gy * W + gx;
#pragma unroll
                        for (int j = 0; j < 8; j++) v[j] = p[j * HW];
                        if (AMODE == 1) {
                            float sv = aux[(size_t)b * HW + (size_t)gy * W + gx];
#pragma unroll
                            for (int j = 0; j < 8; j++) v[j] *= sv;
                        }
                    } else {
#pragma unroll
                        for (int j = 0; j < 8; j++) v[j] = 0.f;
                    }
                }
                uint4 hi4;
                hi4.x = packh2(v[0], v[1]); hi4.y = packh2(v[2], v[3]);
                hi4.z = packh2(v[4], v[5]); hi4.w = packh2(v[6], v[7]);
                uint32_t ad = (uint32_t)ph * 128 + (((o ^ (ph & 7))) << 4);
                *(uint4*)(smem + OFF_A + ad) = hi4;
            }
        }

        for (int grp = 0; grp < GPC; grp++, fg++) {
            int s = fg & 1;
            CPA_WAIT0();
            __syncthreads();

            if (fg + 1 < NGRP) stage_group(fg + 1, s ^ 1);

            int t0 = grp * G;
#pragma unroll
            for (int j = 0; j < G; j++) {
                int tap = t0 + j;
                if (tap < KK) {
                    int tapy = tap / KS, tapx = tap - tapy * KS;
                    uint32_t bbase = sb + OFF_B + s * BSTRIDE + j * 8192;
#pragma unroll
                    for (int kc = 0; kc < 4; kc++) {
                        uint32_t a[4][4];
#pragma unroll
                        for (int t = 0; t < 4; t++) {
                            int y = wm * 2 + (t >> 1);
                            int ph = (y + tapy) * IWP + (t & 1) * 16 + ar + tapx;
                            ldm4(sb + OFF_A + (uint32_t)ph * 128
                                 + ((((kc * 2 + akq) ^ (ph & 7))) << 4), a[t]);
                        }
#pragma unroll
                        for (int g = 0; g < 2; g++) {
                            int n = nh * 32 + g * 16 + br;
                            uint32_t ba = bbase + (uint32_t)n * 128
                                        + ((((kc * 2 + bkq) ^ (n & 7))) << 4);
                            uint32_t bh[4];
                            ldm4(ba, bh);
#pragma unroll
                            for (int t = 0; t < 4; t++) {
                                mma16816(acc[t * 4 + 2 * g],     a[t], bh[0], bh[2]);
                                mma16816(acc[t * 4 + 2 * g + 1], a[t], bh[1], bh[3]);
                            }
                        }
                    }
                }
            }
        }
    }

    // ---- epilogue ----
    __syncthreads();
    float* tb = (float*)(smem + 1024);
    {
        int row = lane >> 2, colp = (lane & 3) * 2;
#pragma unroll
        for (int t = 0; t < 4; t++) {
            int p0 = wm * 64 + t * 16 + row;
#pragma unroll
            for (int j = 0; j < 4; j++) {
                int c = nh * 32 + j * 8 + colp;
                tb[p0 * 65 + c]            = acc[t * 4 + j][0];
                tb[p0 * 65 + c + 1]        = acc[t * 4 + j][1];
                tb[(p0 + 8) * 65 + c]      = acc[t * 4 + j][2];
                tb[(p0 + 8) * 65 + c + 1]  = acc[t * 4 + j][3];
            }
        }
    }
    __syncthreads();
    if (OUTF == 0) {
#pragma unroll 4
        for (int it = 0; it < 64; it++) {
            int item = it * 8 + wid;
            int c = item >> 3, py = item & 7;
            float v = tb[(py * 32 + lane) * 65 + c] * epi[c] + epi[64 + c];
            if (MODE == 1) v = gelu_exact(v);
            outF[((size_t)(b * 64 + c) * H + (y0 + py)) * W + x0 + lane] = v;
        }
    } else {
#pragma unroll
        for (int it = 0; it < 8; it++) {
            int item = it * 256 + tid;
            int px = item >> 3, grp = item & 7;
            float vs[8];
#pragma unroll
            for (int j = 0; j < 8; j++) {
                int c = grp * 8 + j;
                float v = tb[px * 65 + c] * epi[c] + epi[64 + c];
                if (MODE == 1) v = gelu_exact(v);
                vs[j] = v;
            }
            uint4 pk;
            pk.x = packh2(vs[0], vs[1]); pk.y = packh2(vs[2], vs[3]);
            pk.z = packh2(vs[4], vs[5]); pk.w = packh2(vs[6], vs[7]);
            int py = px >> 5, xx = px & 31;
            *(uint4*)(outH + ((((size_t)b * H + y0 + py) * W + x0 + xx) << 6) + grp * 8) = pk;
        }
    }
}

// ---------------- AP_MP diff: CTA-tiled u staging, bil from smem ----------------
// 16x16 output tile per CTA; u patch 18x18 (stride 20) per channel, 32 ch/round.
// Arithmetic expressions identical to prior versions -> bit-identical output.
__global__ __launch_bounds__(256)
void diff_kernel(const float* __restrict__ u, const float* __restrict__ x,
                 float* __restrict__ out)
{
    __shared__ float s_u[32 * 360];            // 32 ch x 18 rows x 20 cols
    int tid = threadIdx.x;
    int j0 = blockIdx.x * 16, i0 = blockIdx.y * 16, b = blockIdx.z;
    int j = j0 + (tid & 15), i = i0 + (tid >> 4);
    const float rr = 95.f / 191.f;

    // per-output sample coordinates (identical formulas)
    float syA = (2 * i) * rr;     int iyA0 = (int)syA; float wyA = syA - (float)iyA0; int iyA1 = min(iyA0 + 1, 95);
    float syB = (2 * i + 1) * rr; int iyB0 = (int)syB; float wyB = syB - (float)iyB0; int iyB1 = min(iyB0 + 1, 95);
    float sxA = (2 * j) * rr;     int ixA0 = (int)sxA; float wxA = sxA - (float)ixA0; int ixA1 = min(ixA0 + 1, 95);
    float sxB = (2 * j + 1) * rr; int ixB0 = (int)sxB; float wxB = sxB - (float)ixB0; int ixB1 = min(ixB0 + 1, 95);

    // patch origin = min sample index within tile (monotonic in i/j)
    int oy = (int)((2 * i0) * rr);
    int ox = (int)((2 * j0) * rr);
    int lyA0 = iyA0 - oy, lyA1 = iyA1 - oy, lyB0 = iyB0 - oy, lyB1 = iyB1 - oy;
    int lxA0 = ixA0 - ox, lxA1 = ixA1 - ox, lxB0 = ixB0 - ox, lxB1 = ixB1 - ox;

    float acc1 = 0.f, acc2 = 0.f;
    size_t xbase = ((size_t)b * 64 * H_ + 2 * i) * W_ + 2 * j;

    for (int c0 = 0; c0 < 64; c0 += 32) {
        __syncthreads();                       // protect prev round's patch
        for (int item = tid; item < 32 * 324; item += 256) {
            int c = item / 324;
            int r = item - c * 324;
            int ry = r / 18, rx = r - ry * 18;
            int gy = oy + ry, gx = ox + rx;
            float v = 0.f;
            if (gy <= 95 && gx <= 95)
                v = u[(size_t)(b * 64 + c0 + c) * 9216 + gy * 96 + gx];
            s_u[c * 360 + ry * 20 + rx] = v;
        }
        __syncthreads();

        for (int c = 0; c < 32; c++) {
            const float* uc = s_u + c * 360;
            float s00 = bil20(uc, lyA0, lyA1, wyA, lxA0, lxA1, wxA);
            float s01 = bil20(uc, lyA0, lyA1, wyA, lxB0, lxB1, wxB);
            float s10 = bil20(uc, lyB0, lyB1, wyB, lxA0, lxA1, wxA);
            float s11 = bil20(uc, lyB0, lyB1, wyB, lxB0, lxB1, wxB);
            float as = 0.25f * (s00 + s01 + s10 + s11);
            float ms = fmaxf(fmaxf(s00, s01), fmaxf(s10, s11));

            size_t base = xbase + (size_t)(c0 + c) * H_ * W_;
            float2 xa = *(const float2*)(x + base);
            float2 xb = *(const float2*)(x + base + W_);
            float ax = 0.25f * (xa.x + xa.y + xb.x + xb.y);
            float mx = fmaxf(fmaxf(xa.x, xa.y), fmaxf(xb.x, xb.y));
            float d1 = as - mx; acc1 += d1 * d1;
            float d2 = ax - ms; acc2 += d2 * d2;
        }
    }
    out[((size_t)b * h_ + i) * w_ + j] = sqrtf(acc1) + sqrtf(acc2);
}

// ---------------- smap: sigmoid(up2(map)) x2 -> (dilate3-map)x2 + 1 ----------------
__global__ __launch_bounds__(256)
void smap_kernel(const float* __restrict__ in_map, const float* __restrict__ ds,
                 float* __restrict__ smap)
{
    __shared__ float s_i[10 * 34];
    __shared__ float s_d[10 * 34];
    int tid = threadIdx.x;
    int x0 = blockIdx.x * 32, y0 = blockIdx.y * 8, b = blockIdx.z;
    const float rr = 95.f / 191.f;
    const float* pi = in_map + (size_t)b * h_ * w_;
    const float* pd = ds + (size_t)b * h_ * w_;

    for (int item = tid; item < 340; item += 256) {
        int hy = item / 34, hx = item - hy * 34;
        int gy = y0 - 1 + hy, gx = x0 - 1 + hx;
        float vi = -INFINITY, vd = -INFINITY;
        if ((unsigned)gy < (unsigned)H_ && (unsigned)gx < (unsigned)W_) {
            float sy = gy * rr; int iy0 = (int)sy; float wy = sy - (float)iy0;
            int iy1 = min(iy0 + 1, h_ - 1);
            float sx = gx * rr; int ix0 = (int)sx; float wx = sx - (float)ix0;
            int ix1 = min(ix0 + 1, w_ - 1);
            float w00 = (1.f - wy) * (1.f - wx), w01 = (1.f - wy) * wx;
            float w10 = wy * (1.f - wx),         w11 = wy * wx;
            float ui = pi[iy0 * w_ + ix0] * w00 + pi[iy0 * w_ + ix1] * w01
                     + pi[iy1 * w_ + ix0] * w10 + pi[iy1 * w_ + ix1] * w11;
            float ud = pd[iy0 * w_ + ix0] * w00 + pd[iy0 * w_ + ix1] * w01
                     + pd[iy1 * w_ + ix0] * w10 + pd[iy1 * w_ + ix1] * w11;
            vi = 1.f / (1.f + expf(-ui));
            vd = 1.f / (1.f + expf(-ud));
        }
        s_i[item] = vi; s_d[item] = vd;
    }
    __syncthreads();

    int tx = tid & 31, ty = tid >> 5;
    int ci = (ty + 1) * 34 + tx + 1;
    float mi = -INFINITY, md = -INFINITY;
#pragma unroll
    for (int dy = 0; dy < 3; dy++)
#pragma unroll
        for (int dx = 0; dx < 3; dx++) {
            int o = (ty + dy) * 34 + tx + dx;
            mi = fmaxf(mi, s_i[o]);
            md = fmaxf(md, s_d[o]);
        }
    float s = (mi - s_i[ci]) + (md - s_d[ci]) + 1.0f;
    smap[((size_t)b * H_ + (y0 + ty)) * W_ + x0 + tx] = s;
}

// ---------------- final conv 7x7, 64 -> 1 (fp32), 4 consecutive px/thread ----------------
// Weights staged with ky rows padded to stride 8 -> vectorized LDS.64 weight loads.
// Accumulation order (c, ky, kx) per output unchanged -> bit-identical.
__global__ __launch_bounds__(256)
void conv_out_kernel(const float* __restrict__ rin, const float* __restrict__ Wo,
                     const float* __restrict__ bo, float* __restrict__ out)
{
    extern __shared__ float s_dyn[];           // 2 x (8*22*70)
    __shared__ float s_w[64 * 56];             // [oc_chan][ky*8 + kx]
    constexpr int BUFE = 8 * 22 * 70;          // 12320 floats
    uint32_t sdb = smem_u32(s_dyn);

    int tid = threadIdx.x;
    int tx4 = tid & 15, ty = tid >> 4;         // 16 x-groups x 16 rows
    int x0 = blockIdx.x * 64, ys = blockIdx.y * 16, b = blockIdx.z;

    for (int idx = tid; idx < 64 * 49; idx += 256) {
        int c = idx / 49, r = idx - c * 49;
        int ky = r / 7, kx = r - ky * 7;
        s_w[c * 56 + ky * 8 + kx] = Wo[idx];
    }

    auto stage = [&](int c0, int buf) {
        float* dst = s_dyn + buf * BUFE;
        uint32_t dbase = sdb + (uint32_t)buf * BUFE * 4;
        for (int idx = tid; idx < BUFE; idx += 256) {
            int c = idx / (22 * 70);
            int r = idx - c * (22 * 70);
            int ly = r / 70, lx = r - ly * 70;
            int gy = ys + ly - 3, gx = x0 + lx - 3;
            if ((unsigned)gy < (unsigned)H_ && (unsigned)gx < (unsigned)W_)
                cpa4(dbase + (uint32_t)idx * 4,
                     rin + ((size_t)(b * 64 + c0 + c) * H_ + gy) * W_ + gx);
            else
                dst[idx] = 0.f;
        }
        CPA_COMMIT();
    };

    stage(0, 0);
    CPA_WAIT0();
    __syncthreads();

    float a0 = 0.f, a1 = 0.f, a2 = 0.f, a3 = 0.f;
    for (int it = 0; it < 8; it++) {
        int buf = it & 1;
        if (it + 1 < 8) stage((it + 1) * 8, buf ^ 1);
        const float* cur = s_dyn + buf * BUFE;
#pragma unroll
        for (int c = 0; c < 8; c++) {
            const float* wrow = &s_w[(it * 8 + c) * 56];
#pragma unroll
            for (int ky = 0; ky < 7; ky++) {
                const float* row = cur + (c * 22 + ty + ky) * 70 + 4 * tx4;
                float2 p0 = *(const float2*)(row + 0);
                float2 p1 = *(const float2*)(row + 2);
                float2 p2 = *(const float2*)(row + 4);
                float2 p3 = *(const float2*)(row + 6);
                float2 p4 = *(const float2*)(row + 8);
                float in[10] = { p0.x, p0.y, p1.x, p1.y, p2.x, p2.y,
                                 p3.x, p3.y, p4.x, p4.y };
                float2 w01 = *(const float2*)(wrow + ky * 8);
                float2 w23 = *(const float2*)(wrow + ky * 8 + 2);
                float2 w45 = *(const float2*)(wrow + ky * 8 + 4);
                float w6   = wrow[ky * 8 + 6];
                float wv[7] = { w01.x, w01.y, w23.x, w23.y, w45.x, w45.y, w6 };
#pragma unroll
                for (int kx = 0; kx < 7; kx++) {
                    float w = wv[kx];
                    a0 += w * in[kx];
                    a1 += w * in[kx + 1];
                    a2 += w * in[kx + 2];
                    a3 += w * in[kx + 3];
                }
            }
        }
        CPA_WAIT0();
        __syncthreads();
    }
    float bv = bo[0];
    float4 res = make_float4(a0 + bv, a1 + bv, a2 + bv, a3 + bv);
    *(float4*)(out + ((size_t)b * H_ + (ys + ty)) * W_ + x0 + 4 * tx4) = res;
}

// ---------------- launch ----------------
#define SMEM_UP (1024 + 14*40*128 + 2*2*8192)   // 105472  (KS=7, G=2)
#define SMEM_3  (1024 + 10*34*128 + 2*3*8192)   // 93696   (KS=3, G=3)
#define SMEM_CO (2*8*22*70*4)                   // 98560

extern "C" void kernel_launch(void* const* d_in, const int* in_sizes, int n_in,
                              void* d_out, int out_size)
{
    const float* x       = (const float*)d_in[0];
    const float* small_x = (const float*)d_in[1];
    const float* in_map  = (const float*)d_in[2];
    const float* W_up  = (const float*)d_in[3];
    const float* b_up  = (const float*)d_in[4];
    const float* gup   = (const float*)d_in[5];
    const float* beup  = (const float*)d_in[6];
    const float* mup   = (const float*)d_in[7];
    const float* vup   = (const float*)d_in[8];
    const float* W_c2  = (const float*)d_in[9];
    const float* b_c2  = (const float*)d_in[10];
    const float* W_d1  = (const float*)d_in[11];
    const float* b_d1  = (const float*)d_in[12];
    const float* gd1   = (const float*)d_in[13];
    const float* bed1  = (const float*)d_in[14];
    const float* md1   = (const float*)d_in[15];
    const float* vd1   = (const float*)d_in[16];
    const float* W_d2  = (const float*)d_in[17];
    const float* b_d2  = (const float*)d_in[18];
    const float* gd2   = (const float*)d_in[19];
    const float* bed2  = (const float*)d_in[20];
    const float* md2   = (const float*)d_in[21];
    const float* vd2   = (const float*)d_in[22];
    const float* W_d3  = (const float*)d_in[23];
    const float* b_d3  = (const float*)d_in[24];
    const float* gd3   = (const float*)d_in[25];
    const float* bed3  = (const float*)d_in[26];
    const float* md3   = (const float*)d_in[27];
    const float* vd3   = (const float*)d_in[28];
    const float* W_out = (const float*)d_in[29];
    const float* b_out = (const float*)d_in[30];
    const float* beta  = (const float*)d_in[31];

    float *u, *ds, *sp;
    __half *fn16, *r116, *r216;
    unsigned char* wbf;
    cudaGetSymbolAddress((void**)&u,    g_u);
    cudaGetSymbolAddress((void**)&ds,   g_diffs);
    cudaGetSymbolAddress((void**)&sp,   g_smap);
    cudaGetSymbolAddress((void**)&fn16, g_fn16);
    cudaGetSymbolAddress((void**)&r116, g_r116);
    cudaGetSymbolAddress((void**)&r216, g_r216);
    cudaGetSymbolAddress((void**)&wbf,  g_wbf);

    cudaFuncSetAttribute(tconv<7,2,2,1,0,0>, cudaFuncAttributeMaxDynamicSharedMemorySize, SMEM_UP);
    cudaFuncSetAttribute(tconv<3,1,3,0,1,1>, cudaFuncAttributeMaxDynamicSharedMemorySize, SMEM_3);
    cudaFuncSetAttribute(tconv<3,2,3,1,2,1>, cudaFuncAttributeMaxDynamicSharedMemorySize, SMEM_3);
    cudaFuncSetAttribute(tconv<3,1,3,1,3,1>, cudaFuncAttributeMaxDynamicSharedMemorySize, SMEM_3);
    cudaFuncSetAttribute(tconv<3,1,3,1,3,0>, cudaFuncAttributeMaxDynamicSharedMemorySize, SMEM_3);
    cudaFuncSetAttribute(conv_out_kernel,    cudaFuncAttributeMaxDynamicSharedMemorySize, SMEM_CO);

    // 1) fused weight prep
    prep_all<<<1024, 256>>>(W_up, W_c2, W_d1, W_d2, W_d3, wbf);

    // 2) up branch: conv7x7 + BN + GELU -> u (96x96 fp32)
    tconv<7,2,2,1,0,0><<<dim3(3, 12, 8), 256, SMEM_UP>>>(
        small_x, nullptr, nullptr, (const uint4*)(wbf + (size_t)CH_UP * 16384),
        b_up, gup, beup, mup, vup, nullptr, u, nullptr, h_, w_);

    // 3) uncertainty maps
    diff_kernel<<<dim3(6, 6, 8), 256>>>(u, x, ds);
    smap_kernel<<<dim3(6, 24, 8), 256>>>(in_map, ds, sp);

    // 4) conv chain (HMMA fp16; inter-layer buffers fp16 NHWC)
    tconv<3,1,3,0,1,1><<<dim3(6, 24, 8), 256, SMEM_3>>>(
        x, nullptr, sp, (const uint4*)(wbf + (size_t)CH_C2 * 16384),
        b_c2, nullptr, nullptr, nullptr, nullptr, beta, nullptr, fn16, H_, W_);
    tconv<3,2,3,1,2,1><<<dim3(6, 24, 8), 256, SMEM_3>>>(
        nullptr, fn16, u, (const uint4*)(wbf + (size_t)CH_D1 * 16384),
        b_d1, gd1, bed1, md1, vd1, nullptr, nullptr, r116, H_, W_);
    tconv<3,1,3,1,3,1><<<dim3(6, 24, 8), 256, SMEM_3>>>(
        nullptr, r116, nullptr, (const uint4*)(wbf + (size_t)CH_D2 * 16384),
        b_d2, gd2, bed2, md2, vd2, nullptr, nullptr, r216, H_, W_);
    tconv<3,1,3,1,3,0><<<dim3(6, 24, 8), 256, SMEM_3>>>(
        nullptr, r216, nullptr, (const uint4*)(wbf + (size_t)CH_D3 * 16384),
        b_d3, gd3, bed3, md3, vd3, nullptr, (float*)d_out, nullptr, H_, W_);

    // 5) output head (reads r from d_out, writes output_map after it)
    conv_out_kernel<<<dim3(3, 12, 8), 256, SMEM_CO>>>(
        (const float*)d_out, W_out, b_out, (float*)d_out + R_ELEMS);
}

// round 15
// speedup vs baseline: 1.4930x; 1.4930x over previous
#include <cuda_runtime.h>
#include <cuda_fp16.h>
#include <math.h>
#include <stdint.h>

// ---------------- problem constants ----------------
#define B_ 8
#define H_ 192
#define W_ 192
#define h_ 96
#define w_ 96
#define R_ELEMS (B_*64*H_*W_)        // 18,874,368

// weight-chunk table (each chunk = 16KB: 8KB hi + 8KB lo, [n][k] swizzled fp16)
#define CH_UP 0      // 7x7, CG=2 -> 98 chunks
#define CH_C2 98     // 3x3, CG=1 -> 9
#define CH_D1 107    // 3x3, CG=2 -> 18
#define CH_D2 125    // 9
#define CH_D3 134    // 9
#define CH_TOTAL 143

// ---------------- scratch ----------------
__device__ __align__(16) unsigned char g_wbf[CH_TOTAL * 16384];
__device__ float g_u[B_*64*h_*w_];
__device__ float g_diffs[B_*h_*w_];
__device__ float g_smap[B_*H_*W_];
__device__ __align__(16) __half g_fn16[R_ELEMS];   // NHWC fp16
__device__ __align__(16) __half g_r116[R_ELEMS];   // NHWC fp16
__device__ __align__(16) __half g_r216[R_ELEMS];   // NHWC fp16

// ---------------- helpers ----------------
__device__ __forceinline__ uint32_t smem_u32(const void* p) {
    uint32_t a;
    asm("{ .reg .u64 t; cvta.to.shared.u64 t, %1; cvt.u32.u64 %0, t; }" : "=r"(a) : "l"(p));
    return a;
}
__device__ __forceinline__ void ldm4(uint32_t addr, uint32_t r[4]) {
    asm volatile("ldmatrix.sync.aligned.m8n8.x4.shared.b16 {%0,%1,%2,%3}, [%4];"
                 : "=r"(r[0]), "=r"(r[1]), "=r"(r[2]), "=r"(r[3]) : "r"(addr));
}
__device__ __forceinline__ void mma16816(float c[4], const uint32_t a[4],
                                         uint32_t b0, uint32_t b1) {
    asm volatile(
        "mma.sync.aligned.m16n8k16.row.col.f32.f16.f16.f32 "
        "{%0,%1,%2,%3}, {%4,%5,%6,%7}, {%8,%9}, {%0,%1,%2,%3};"
        : "+f"(c[0]), "+f"(c[1]), "+f"(c[2]), "+f"(c[3])
        : "r"(a[0]), "r"(a[1]), "r"(a[2]), "r"(a[3]), "r"(b0), "r"(b1));
}
__device__ __forceinline__ void cpa16(uint32_t saddr, const void* g) {
    asm volatile("cp.async.cg.shared.global [%0], [%1], 16;" :: "r"(saddr), "l"(g) : "memory");
}
__device__ __forceinline__ void cpa4(uint32_t saddr, const void* g) {
    asm volatile("cp.async.ca.shared.global [%0], [%1], 4;" :: "r"(saddr), "l"(g) : "memory");
}
#define CPA_COMMIT() asm volatile("cp.async.commit_group;" ::: "memory")
#define CPA_WAIT0()  asm volatile("cp.async.wait_group 0;" ::: "memory")

__device__ __forceinline__ float gelu_exact(float y) {
    return 0.5f * y * (1.0f + erff(y * 0.70710678118654752f));
}
__device__ __forceinline__ uint32_t packh2(float a, float b) {
    __half2 h = __floats2half2_rn(a, b);
    return *(uint32_t*)&h;
}
// bilinear sample matching the original up2_kernel's exact fp32 expression order
__device__ __forceinline__ float bil96(const float* p, int iy0, int iy1, float wy,
                                       int ix0, int ix1, float wx) {
    float a = p[iy0 * 96 + ix0], b = p[iy1 * 96 + ix0];
    float c = p[iy0 * 96 + ix1], d = p[iy1 * 96 + ix1];
    float ra = a * (1.f - wy) + b * wy;
    float rb = c * (1.f - wy) + d * wy;
    return ra * (1.f - wx) + rb * wx;
}

// ---------------- fused weight prep: all 5 conv weight sets ----------------
__global__ void prep_all(const float* __restrict__ W_up, const float* __restrict__ W_c2,
                         const float* __restrict__ W_d1, const float* __restrict__ W_d2,
                         const float* __restrict__ W_d3, unsigned char* __restrict__ dst)
{
    int total = CH_TOTAL * 4096;
    for (int idx = blockIdx.x * blockDim.x + threadIdx.x; idx < total;
         idx += gridDim.x * blockDim.x) {
        int chunk = idx >> 12;
        int e = idx & 4095;
        int n = e >> 6, k = e & 63;
        const float* W; int CIN, KK, local;
        if (chunk < 98)       { W = W_up; CIN = 128; KK = 49; local = chunk; }
        else if (chunk < 107) { W = W_c2; CIN = 64;  KK = 9;  local = chunk - 98; }
        else if (chunk < 125) { W = W_d1; CIN = 128; KK = 9;  local = chunk - 107; }
        else if (chunk < 134) { W = W_d2; CIN = 64;  KK = 9;  local = chunk - 125; }
        else                  { W = W_d3; CIN = 64;  KK = 9;  local = chunk - 134; }
        int CG = CIN >> 6;
        int tap = local / CG, cg = local - tap * CG;
        float w = W[((size_t)n * CIN + cg * 64 + k) * KK + tap];
        __half hb = __float2half_rn(w);
        __half lb = __float2half_rn(w - __half2float(hb));
        uint32_t off = (uint32_t)n * 128 + ((((k >> 3) ^ (n & 7))) << 4) + (k & 7) * 2;
        unsigned char* base = dst + (size_t)chunk * 16384;
        *(unsigned short*)(base + off)        = __half_as_ushort(hb);
        *(unsigned short*)(base + 8192 + off) = __half_as_ushort(lb);
    }
}

// ---------------- HMMA implicit-GEMM conv (group-staged weights) ----------------
// TM=8 rows x 32 px per CTA (M=256), 64 out chans; warp tile m64 x n32.
// AMODE 0: input = inA (fp32 NCHW).  AMODE 1: inA * aux(smap).
// AMODE 2: cg0 = bilinear-up2(aux = u), cg1 = inH (fp16 NHWC).
// AMODE 3: input = inH (fp16 NHWC).
// MODE 0: beta*(acc+bias)   MODE 1: gelu(bn(acc+bias))
// OUTF 0: fp32 NCHW (outF)  OUTF 1: fp16 NHWC (outH)
template<int KS, int CG, int G, int MODE, int AMODE, int OUTF>
__global__ __launch_bounds__(256, 2)
void tconv(const float* __restrict__ inA, const __half* __restrict__ inH,
           const float* __restrict__ aux,
           const uint4* __restrict__ wch, const float* __restrict__ bias,
           const float* __restrict__ gg, const float* __restrict__ bb,
           const float* __restrict__ mm, const float* __restrict__ vv,
           const float* __restrict__ betap,
           float* __restrict__ outF, __half* __restrict__ outH,
           int H, int W)
{
    constexpr int PAD = KS / 2;
    constexpr int TM  = 8;
    constexpr int IH  = TM + KS - 1;
    constexpr int IWP = (KS == 3) ? 34 : 40;
    constexpr int NPX = IH * IWP;
    constexpr int KK  = KS * KS;
    constexpr int GPC = (KK + G - 1) / G;
    constexpr int NGRP = GPC * CG;
    constexpr int OFF_A = 1024;
    constexpr int OFF_B = 1024 + NPX * 128;
    constexpr int BSTRIDE = G * 8192;

    extern __shared__ char smem_raw[];
    char* smem = (char*)(((uintptr_t)smem_raw + 1023) & ~(uintptr_t)1023);
    uint32_t sb = smem_u32(smem);
    float* epi = (float*)smem;

    int tid = threadIdx.x, wid = tid >> 5, lane = tid & 31;
    int x0 = blockIdx.x * 32, y0 = blockIdx.y * TM, b = blockIdx.z;
    size_t HW = (size_t)H * W;

    auto stage_group = [&](int fg, int buf) {
        int cgg = fg / GPC, grp = fg - cgg * GPC;
        int t0 = grp * G;
        int cnt = (KK - t0 < G) ? (KK - t0) : G;
        for (int j = 0; j < cnt; j++) {
            int chunk = (t0 + j) * CG + cgg;
            const uint4* srcB = wch + (size_t)chunk * 1024;
            uint32_t dstB = sb + OFF_B + buf * BSTRIDE + j * 8192;
#pragma unroll
            for (int k = 0; k < 2; k++)
                cpa16(dstB + (uint32_t)(tid + k * 256) * 16, srcB + tid + k * 256);
        }
        CPA_COMMIT();
    };

    stage_group(0, 0);

    if (tid < 64) {
        int c = tid;
        float s, t;
        if (MODE == 1) {
            s = gg[c] * rsqrtf(vv[c] + 1e-5f);
            t = (bias[c] - mm[c]) * s + bb[c];
        } else {
            float bt = *betap;
            s = bt; t = bt * bias[c];
        }
        epi[c] = s; epi[64 + c] = t;
    }

    float acc[16][4];
#pragma unroll
    for (int i = 0; i < 16; i++)
#pragma unroll
        for (int j = 0; j < 4; j++) acc[i][j] = 0.f;

    int wm = wid >> 1, nh = wid & 1;
    int ar = lane & 15, akq = lane >> 4;
    int br = lane & 15, bkq = lane >> 4;

    int fg = 0;
    for (int cg = 0; cg < CG; cg++) {
        __syncthreads();

        // ---- stage halo ----
        constexpr int TOT = NPX * 8;
        bool h16 = (AMODE == 3) || (AMODE == 2 && CG == 2);
        if (h16 && (AMODE == 3 || cg == 1)) {
            for (int item = tid; item < TOT; item += 256) {
                int ph = item >> 3, o = item & 7;
                int hy = ph / IWP, hx = ph - hy * IWP;
                int gy = y0 + hy - PAD;
                int gx = x0 + hx - PAD;
                uint4 val = make_uint4(0, 0, 0, 0);
                if ((unsigned)gy < (unsigned)H && (unsigned)gx < (unsigned)W)
                    val = *(const uint4*)(inH + ((((size_t)b * H + gy) * W + gx) << 6) + o * 8);
                uint32_t ad = (uint32_t)ph * 128 + (((o ^ (ph & 7))) << 4);
                *(uint4*)(smem + OFF_A + ad) = val;
            }
        } else {
            const float* src = nullptr;
            if (AMODE != 2) src = inA + ((size_t)b * (CG * 64) + cg * 64) * HW;
            const float rr = 95.f / 191.f;
            for (int item = tid; item < TOT; item += 256) {
                int o  = item / NPX;
                int ph = item - o * NPX;
                int hy = ph / IWP, hx = ph - hy * IWP;
                int gy = y0 + hy - PAD;
                int gx = x0 + hx - PAD;
                float v[8];
                bool inb = (unsigned)gy < (unsigned)H && (unsigned)gx < (unsigned)W;
                if (AMODE == 2) {
                    if (inb) {
                        float sy = gy * rr; int iy0 = (int)sy; float wy = sy - (float)iy0;
                        int iy1 = min(iy0 + 1, 95);
                        float sx = gx * rr; int ix0 = (int)sx; float wx = sx - (float)ix0;
                        int ix1 = min(ix0 + 1, 95);
                        const float* up = aux + (size_t)(b * 64 + o * 8) * 9216;
#pragma unroll
                        for (int j = 0; j < 8; j++)
                            v[j] = bil96(up + j * 9216, iy0, iy1, wy, ix0, ix1, wx);
                    } else {
#pragma unroll
                        for (int j = 0; j < 8; j++) v[j] = 0.f;
                    }
                } else {
                    if (inb) {
                        const float* p = src + (size_t)(o * 8) * HW + (size_t)gy * W + gx;
#pragma unroll
                        for (int j = 0; j < 8; j++) v[j] = p[j * HW];
                        if (AMODE == 1) {
                            float sv = aux[(size_t)b * HW + (size_t)gy * W + gx];
#pragma unroll
                            for (int j = 0; j < 8; j++) v[j] *= sv;
                        }
                    } else {
#pragma unroll
                        for (int j = 0; j < 8; j++) v[j] = 0.f;
                    }
                }
                uint4 hi4;
                hi4.x = packh2(v[0], v[1]); hi4.y = packh2(v[2], v[3]);
                hi4.z = packh2(v[4], v[5]); hi4.w = packh2(v[6], v[7]);
                uint32_t ad = (uint32_t)ph * 128 + (((o ^ (ph & 7))) << 4);
                *(uint4*)(smem + OFF_A + ad) = hi4;
            }
        }

        for (int grp = 0; grp < GPC; grp++, fg++) {
            int s = fg & 1;
            CPA_WAIT0();
            __syncthreads();

            if (fg + 1 < NGRP) stage_group(fg + 1, s ^ 1);

            int t0 = grp * G;
#pragma unroll
            for (int j = 0; j < G; j++) {
                int tap = t0 + j;
                if (tap < KK) {
                    int tapy = tap / KS, tapx = tap - tapy * KS;
                    uint32_t bbase = sb + OFF_B + s * BSTRIDE + j * 8192;
#pragma unroll
                    for (int kc = 0; kc < 4; kc++) {
                        uint32_t a[4][4];
#pragma unroll
                        for (int t = 0; t < 4; t++) {
                            int y = wm * 2 + (t >> 1);
                            int ph = (y + tapy) * IWP + (t & 1) * 16 + ar + tapx;
                            ldm4(sb + OFF_A + (uint32_t)ph * 128
                                 + ((((kc * 2 + akq) ^ (ph & 7))) << 4), a[t]);
                        }
#pragma unroll
                        for (int g = 0; g < 2; g++) {
                            int n = nh * 32 + g * 16 + br;
                            uint32_t ba = bbase + (uint32_t)n * 128
                                        + ((((kc * 2 + bkq) ^ (n & 7))) << 4);
                            uint32_t bh[4];
                            ldm4(ba, bh);
#pragma unroll
                            for (int t = 0; t < 4; t++) {
                                mma16816(acc[t * 4 + 2 * g],     a[t], bh[0], bh[2]);
                                mma16816(acc[t * 4 + 2 * g + 1], a[t], bh[1], bh[3]);
                            }
                        }
                    }
                }
            }
        }
    }

    // ---- epilogue ----
    __syncthreads();
    float* tb = (float*)(smem + 1024);
    {
        int row = lane >> 2, colp = (lane & 3) * 2;
#pragma unroll
        for (int t = 0; t < 4; t++) {
            int p0 = wm * 64 + t * 16 + row;
#pragma unroll
            for (int j = 0; j < 4; j++) {
                int c = nh * 32 + j * 8 + colp;
                tb[p0 * 65 + c]            = acc[t * 4 + j][0];
                tb[p0 * 65 + c + 1]        = acc[t * 4 + j][1];
                tb[(p0 + 8) * 65 + c]      = acc[t * 4 + j][2];
                tb[(p0 + 8) * 65 + c + 1]  = acc[t * 4 + j][3];
            }
        }
    }
    __syncthreads();
    if (OUTF == 0) {
#pragma unroll 4
        for (int it = 0; it < 64; it++) {
            int item = it * 8 + wid;
            int c = item >> 3, py = item & 7;
            float v = tb[(py * 32 + lane) * 65 + c] * epi[c] + epi[64 + c];
            if (MODE == 1) v = gelu_exact(v);
            outF[((size_t)(b * 64 + c) * H + (y0 + py)) * W + x0 + lane] = v;
        }
    } else {
#pragma unroll
        for (int it = 0; it < 8; it++) {
            int item = it * 256 + tid;
            int px = item >> 3, grp = item & 7;
            float vs[8];
#pragma unroll
            for (int j = 0; j < 8; j++) {
                int c = grp * 8 + j;
                float v = tb[px * 65 + c] * epi[c] + epi[64 + c];
                if (MODE == 1) v = gelu_exact(v);
                vs[j] = v;
            }
            uint4 pk;
            pk.x = packh2(vs[0], vs[1]); pk.y = packh2(vs[2], vs[3]);
            pk.z = packh2(vs[4], vs[5]); pk.w = packh2(vs[6], vs[7]);
            int py = px >> 5, xx = px & 31;
            *(uint4*)(outH + ((((size_t)b * H + y0 + py) * W + x0 + xx) << 6) + grp * 8) = pk;
        }
    }
}

// ---------------- AP_MP diff with inline up2(u), 2 outputs/thread ----------------
__global__ void diff_kernel(const float* __restrict__ u, const float* __restrict__ x,
                            float* __restrict__ out)
{
    int idx = blockIdx.x * blockDim.x + threadIdx.x;
    if (idx >= B_ * h_ * (w_ / 2)) return;
    int jp = idx % (w_ / 2);
    int t = idx / (w_ / 2);
    int i = t % h_;
    int b = t / h_;
    int j0 = 2 * jp;
    const float rr = 95.f / 191.f;

    float syA = (2 * i) * rr;     int iyA0 = (int)syA; float wyA = syA - (float)iyA0; int iyA1 = min(iyA0 + 1, 95);
    float syB = (2 * i + 1) * rr; int iyB0 = (int)syB; float wyB = syB - (float)iyB0; int iyB1 = min(iyB0 + 1, 95);

    float sxA0 = (2 * j0) * rr;     int ixA00 = (int)sxA0; float wxA0 = sxA0 - (float)ixA00; int ixA01 = min(ixA00 + 1, 95);
    float sxB0 = (2 * j0 + 1) * rr; int ixB00 = (int)sxB0; float wxB0 = sxB0 - (float)ixB00; int ixB01 = min(ixB00 + 1, 95);
    float sxA1 = (2 * j0 + 2) * rr; int ixA10 = (int)sxA1; float wxA1 = sxA1 - (float)ixA10; int ixA11 = min(ixA10 + 1, 95);
    float sxB1 = (2 * j0 + 3) * rr; int ixB10 = (int)sxB1; float wxB1 = sxB1 - (float)ixB10; int ixB11 = min(ixB10 + 1, 95);

    float a1_0 = 0.f, a2_0 = 0.f, a1_1 = 0.f, a2_1 = 0.f;
    size_t base0 = ((size_t)b * 64 * H_ + 2 * i) * W_ + 4 * jp;
    for (int c = 0; c < 64; c++) {
        const float* uc = u + (size_t)(b * 64 + c) * 9216;
        size_t base = base0 + (size_t)c * H_ * W_;
        float4 xr0 = *(const float4*)(x + base);
        float4 xr1 = *(const float4*)(x + base + W_);

        {
            float s00 = bil96(uc, iyA0, iyA1, wyA, ixA00, ixA01, wxA0);
            float s01 = bil96(uc, iyA0, iyA1, wyA, ixB00, ixB01, wxB0);
            float s10 = bil96(uc, iyB0, iyB1, wyB, ixA00, ixA01, wxA0);
            float s11 = bil96(uc, iyB0, iyB1, wyB, ixB00, ixB01, wxB0);
            float as = 0.25f * (s00 + s01 + s10 + s11);
            float ms = fmaxf(fmaxf(s00, s01), fmaxf(s10, s11));
            float ax = 0.25f * (xr0.x + xr0.y + xr1.x + xr1.y);
            float mx = fmaxf(fmaxf(xr0.x, xr0.y), fmaxf(xr1.x, xr1.y));
            float d1 = as - mx; a1_0 += d1 * d1;
            float d2 = ax - ms; a2_0 += d2 * d2;
        }
        {
            float s00 = bil96(uc, iyA0, iyA1, wyA, ixA10, ixA11, wxA1);
            float s01 = bil96(uc, iyA0, iyA1, wyA, ixB10, ixB11, wxB1);
            float s10 = bil96(uc, iyB0, iyB1, wyB, ixA10, ixA11, wxA1);
            float s11 = bil96(uc, iyB0, iyB1, wyB, ixB10, ixB11, wxB1);
            float as = 0.25f * (s00 + s01 + s10 + s11);
            float ms = fmaxf(fmaxf(s00, s01), fmaxf(s10, s11));
            float ax = 0.25f * (xr0.z + xr0.w + xr1.z + xr1.w);
            float mx = fmaxf(fmaxf(xr0.z, xr0.w), fmaxf(xr1.z, xr1.w));
            float d1 = as - mx; a1_1 += d1 * d1;
            float d2 = ax - ms; a2_1 += d2 * d2;
        }
    }
    size_t ob = ((size_t)b * h_ + i) * w_ + j0;
    out[ob]     = sqrtf(a1_0) + sqrtf(a2_0);
    out[ob + 1] = sqrtf(a1_1) + sqrtf(a2_1);
}

// ---------------- smap: sigmoid(up2(map)) x2 -> (dilate3-map)x2 + 1 ----------------
__global__ __launch_bounds__(256)
void smap_kernel(const float* __restrict__ in_map, const float* __restrict__ ds,
                 float* __restrict__ smap)
{
    __shared__ float s_i[10 * 34];
    __shared__ float s_d[10 * 34];
    int tid = threadIdx.x;
    int x0 = blockIdx.x * 32, y0 = blockIdx.y * 8, b = blockIdx.z;
    const float rr = 95.f / 191.f;
    const float* pi = in_map + (size_t)b * h_ * w_;
    const float* pd = ds + (size_t)b * h_ * w_;

    for (int item = tid; item < 340; item += 256) {
        int hy = item / 34, hx = item - hy * 34;
        int gy = y0 - 1 + hy, gx = x0 - 1 + hx;
        float vi = -INFINITY, vd = -INFINITY;
        if ((unsigned)gy < (unsigned)H_ && (unsigned)gx < (unsigned)W_) {
            float sy = gy * rr; int iy0 = (int)sy; float wy = sy - (float)iy0;
            int iy1 = min(iy0 + 1, h_ - 1);
            float sx = gx * rr; int ix0 = (int)sx; float wx = sx - (float)ix0;
            int ix1 = min(ix0 + 1, w_ - 1);
            float w00 = (1.f - wy) * (1.f - wx), w01 = (1.f - wy) * wx;
            float w10 = wy * (1.f - wx),         w11 = wy * wx;
            float ui = pi[iy0 * w_ + ix0] * w00 + pi[iy0 * w_ + ix1] * w01
                     + pi[iy1 * w_ + ix0] * w10 + pi[iy1 * w_ + ix1] * w11;
            float ud = pd[iy0 * w_ + ix0] * w00 + pd[iy0 * w_ + ix1] * w01
                     + pd[iy1 * w_ + ix0] * w10 + pd[iy1 * w_ + ix1] * w11;
            vi = 1.f / (1.f + expf(-ui));
            vd = 1.f / (1.f + expf(-ud));
        }
        s_i[item] = vi; s_d[item] = vd;
    }
    __syncthreads();

    int tx = tid & 31, ty = tid >> 5;
    int ci = (ty + 1) * 34 + tx + 1;
    float mi = -INFINITY, md = -INFINITY;
#pragma unroll
    for (int dy = 0; dy < 3; dy++)
#pragma unroll
        for (int dx = 0; dx < 3; dx++) {
            int o = (ty + dy) * 34 + tx + dx;
            mi = fmaxf(mi, s_i[o]);
            md = fmaxf(md, s_d[o]);
        }
    float s = (mi - s_i[ci]) + (md - s_d[ci]) + 1.0f;
    smap[((size_t)b * H_ + (y0 + ty)) * W_ + x0 + tx] = s;
}

// ---------------- final conv 7x7, 64 -> 1 (fp32), 4 consecutive px/thread ----------------
__global__ __launch_bounds__(256)
void conv_out_kernel(const float* __restrict__ rin, const float* __restrict__ Wo,
                     const float* __restrict__ bo, float* __restrict__ out)
{
    extern __shared__ float s_dyn[];           // 2 x (8*22*70)
    __shared__ float s_w[64 * 49];
    constexpr int BUFE = 8 * 22 * 70;          // 12320 floats
    uint32_t sdb = smem_u32(s_dyn);

    int tid = threadIdx.x;
    int tx4 = tid & 15, ty = tid >> 4;         // 16 x-groups x 16 rows
    int x0 = blockIdx.x * 64, ys = blockIdx.y * 16, b = blockIdx.z;

    for (int idx = tid; idx < 64 * 49; idx += 256)
        s_w[idx] = Wo[idx];

    auto stage = [&](int c0, int buf) {
        float* dst = s_dyn + buf * BUFE;
        uint32_t dbase = sdb + (uint32_t)buf * BUFE * 4;
        for (int idx = tid; idx < BUFE; idx += 256) {
            int c = idx / (22 * 70);
            int r = idx - c * (22 * 70);
            int ly = r / 70, lx = r - ly * 70;
            int gy = ys + ly - 3, gx = x0 + lx - 3;
            if ((unsigned)gy < (unsigned)H_ && (unsigned)gx < (unsigned)W_)
                cpa4(dbase + (uint32_t)idx * 4,
                     rin + ((size_t)(b * 64 + c0 + c) * H_ + gy) * W_ + gx);
            else
                dst[idx] = 0.f;
        }
        CPA_COMMIT();
    };

    stage(0, 0);
    CPA_WAIT0();
    __syncthreads();

    float a0 = 0.f, a1 = 0.f, a2 = 0.f, a3 = 0.f;
    for (int it = 0; it < 8; it++) {
        int buf = it & 1;
        if (it + 1 < 8) stage((it + 1) * 8, buf ^ 1);
        const float* cur = s_dyn + buf * BUFE;
#pragma unroll
        for (int c = 0; c < 8; c++) {
            const float* wrow = &s_w[(it * 8 + c) * 49];
#pragma unroll
            for (int ky = 0; ky < 7; ky++) {
                const float* row = cur + (c * 22 + ty + ky) * 70 + 4 * tx4;
                // 10-value window via 5 aligned float2 loads
                float2 p0 = *(const float2*)(row + 0);
                float2 p1 = *(const float2*)(row + 2);
                float2 p2 = *(const float2*)(row + 4);
                float2 p3 = *(const float2*)(row + 6);
                float2 p4 = *(const float2*)(row + 8);
                float in[10] = { p0.x, p0.y, p1.x, p1.y, p2.x, p2.y,
                                 p3.x, p3.y, p4.x, p4.y };
#pragma unroll
                for (int kx = 0; kx < 7; kx++) {
                    float w = wrow[ky * 7 + kx];
                    a0 += w * in[kx];
                    a1 += w * in[kx + 1];
                    a2 += w * in[kx + 2];
                    a3 += w * in[kx + 3];
                }
            }
        }
        CPA_WAIT0();
        __syncthreads();
    }
    float bv = bo[0];
    float4 res = make_float4(a0 + bv, a1 + bv, a2 + bv, a3 + bv);
    *(float4*)(out + ((size_t)b * H_ + (ys + ty)) * W_ + x0 + 4 * tx4) = res;
}

// ---------------- launch ----------------
#define SMEM_UP (1024 + 14*40*128 + 2*2*8192)   // 105472  (KS=7, G=2)
#define SMEM_3  (1024 + 10*34*128 + 2*3*8192)   // 93696   (KS=3, G=3)
#define SMEM_CO (2*8*22*70*4)                   // 98560

extern "C" void kernel_launch(void* const* d_in, const int* in_sizes, int n_in,
                              void* d_out, int out_size)
{
    const float* x       = (const float*)d_in[0];
    const float* small_x = (const float*)d_in[1];
    const float* in_map  = (const float*)d_in[2];
    const float* W_up  = (const float*)d_in[3];
    const float* b_up  = (const float*)d_in[4];
    const float* gup   = (const float*)d_in[5];
    const float* beup  = (const float*)d_in[6];
    const float* mup   = (const float*)d_in[7];
    const float* vup   = (const float*)d_in[8];
    const float* W_c2  = (const float*)d_in[9];
    const float* b_c2  = (const float*)d_in[10];
    const float* W_d1  = (const float*)d_in[11];
    const float* b_d1  = (const float*)d_in[12];
    const float* gd1   = (const float*)d_in[13];
    const float* bed1  = (const float*)d_in[14];
    const float* md1   = (const float*)d_in[15];
    const float* vd1   = (const float*)d_in[16];
    const float* W_d2  = (const float*)d_in[17];
    const float* b_d2  = (const float*)d_in[18];
    const float* gd2   = (const float*)d_in[19];
    const float* bed2  = (const float*)d_in[20];
    const float* md2   = (const float*)d_in[21];
    const float* vd2   = (const float*)d_in[22];
    const float* W_d3  = (const float*)d_in[23];
    const float* b_d3  = (const float*)d_in[24];
    const float* gd3   = (const float*)d_in[25];
    const float* bed3  = (const float*)d_in[26];
    const float* md3   = (const float*)d_in[27];
    const float* vd3   = (const float*)d_in[28];
    const float* W_out = (const float*)d_in[29];
    const float* b_out = (const float*)d_in[30];
    const float* beta  = (const float*)d_in[31];

    float *u, *ds, *sp;
    __half *fn16, *r116, *r216;
    unsigned char* wbf;
    cudaGetSymbolAddress((void**)&u,    g_u);
    cudaGetSymbolAddress((void**)&ds,   g_diffs);
    cudaGetSymbolAddress((void**)&sp,   g_smap);
    cudaGetSymbolAddress((void**)&fn16, g_fn16);
    cudaGetSymbolAddress((void**)&r116, g_r116);
    cudaGetSymbolAddress((void**)&r216, g_r216);
    cudaGetSymbolAddress((void**)&wbf,  g_wbf);

    cudaFuncSetAttribute(tconv<7,2,2,1,0,0>, cudaFuncAttributeMaxDynamicSharedMemorySize, SMEM_UP);
    cudaFuncSetAttribute(tconv<3,1,3,0,1,1>, cudaFuncAttributeMaxDynamicSharedMemorySize, SMEM_3);
    cudaFuncSetAttribute(tconv<3,2,3,1,2,1>, cudaFuncAttributeMaxDynamicSharedMemorySize, SMEM_3);
    cudaFuncSetAttribute(tconv<3,1,3,1,3,1>, cudaFuncAttributeMaxDynamicSharedMemorySize, SMEM_3);
    cudaFuncSetAttribute(tconv<3,1,3,1,3,0>, cudaFuncAttributeMaxDynamicSharedMemorySize, SMEM_3);
    cudaFuncSetAttribute(conv_out_kernel,    cudaFuncAttributeMaxDynamicSharedMemorySize, SMEM_CO);

    // 1) fused weight prep
    prep_all<<<1024, 256>>>(W_up, W_c2, W_d1, W_d2, W_d3, wbf);

    // 2) up branch: conv7x7 + BN + GELU -> u (96x96 fp32)
    tconv<7,2,2,1,0,0><<<dim3(3, 12, 8), 256, SMEM_UP>>>(
        small_x, nullptr, nullptr, (const uint4*)(wbf + (size_t)CH_UP * 16384),
        b_up, gup, beup, mup, vup, nullptr, u, nullptr, h_, w_);

    // 3) uncertainty maps
    diff_kernel<<<(B_ * h_ * (w_ / 2) + 255) / 256, 256>>>(u, x, ds);
    smap_kernel<<<dim3(6, 24, 8), 256>>>(in_map, ds, sp);

    // 4) conv chain (HMMA fp16; inter-layer buffers fp16 NHWC)
    tconv<3,1,3,0,1,1><<<dim3(6, 24, 8), 256, SMEM_3>>>(
        x, nullptr, sp, (const uint4*)(wbf + (size_t)CH_C2 * 16384),
        b_c2, nullptr, nullptr, nullptr, nullptr, beta, nullptr, fn16, H_, W_);
    tconv<3,2,3,1,2,1><<<dim3(6, 24, 8), 256, SMEM_3>>>(
        nullptr, fn16, u, (const uint4*)(wbf + (size_t)CH_D1 * 16384),
        b_d1, gd1, bed1, md1, vd1, nullptr, nullptr, r116, H_, W_);
    tconv<3,1,3,1,3,1><<<dim3(6, 24, 8), 256, SMEM_3>>>(
        nullptr, r116, nullptr, (const uint4*)(wbf + (size_t)CH_D2 * 16384),
        b_d2, gd2, bed2, md2, vd2, nullptr, nullptr, r216, H_, W_);
    tconv<3,1,3,1,3,0><<<dim3(6, 24, 8), 256, SMEM_3>>>(
        nullptr, r216, nullptr, (const uint4*)(wbf + (size_t)CH_D3 * 16384),
        b_d3, gd3, bed3, md3, vd3, nullptr, (float*)d_out, nullptr, H_, W_);

    // 5) output head (reads r from d_out, writes output_map after it)
    conv_out_kernel<<<dim3(3, 12, 8), 256, SMEM_CO>>>(
        (const float*)d_out, W_out, b_out, (float*)d_out + R_ELEMS);
}

// round 16
// speedup vs baseline: 1.5004x; 1.0050x over previous
#include <cuda_runtime.h>
#include <cuda_fp16.h>
#include <math.h>
#include <stdint.h>

// ---------------- problem constants ----------------
#define B_ 8
#define H_ 192
#define W_ 192
#define h_ 96
#define w_ 96
#define R_ELEMS (B_*64*H_*W_)        // 18,874,368

// weight-chunk table (each chunk = 16KB: 8KB hi + 8KB lo, [n][k] swizzled fp16)
#define CH_UP 0      // 7x7, CG=2 -> 98 chunks
#define CH_C2 98     // 3x3, CG=1 -> 9
#define CH_D1 107    // 3x3, CG=2 -> 18
#define CH_D2 125    // 9
#define CH_D3 134    // 9
#define CH_TOTAL 143

// ---------------- scratch ----------------
__device__ __align__(16) unsigned char g_wbf[CH_TOTAL * 16384];
__device__ float g_u[B_*64*h_*w_];
__device__ float g_diffs[B_*h_*w_];
__device__ float g_smap[B_*H_*W_];
__device__ __align__(16) __half g_fn16[R_ELEMS];   // NHWC fp16
__device__ __align__(16) __half g_r116[R_ELEMS];   // NHWC fp16
__device__ __align__(16) __half g_r216[R_ELEMS];   // NHWC fp16

// ---------------- helpers ----------------
__device__ __forceinline__ uint32_t smem_u32(const void* p) {
    uint32_t a;
    asm("{ .reg .u64 t; cvta.to.shared.u64 t, %1; cvt.u32.u64 %0, t; }" : "=r"(a) : "l"(p));
    return a;
}
__device__ __forceinline__ void ldm4(uint32_t addr, uint32_t r[4]) {
    asm volatile("ldmatrix.sync.aligned.m8n8.x4.shared.b16 {%0,%1,%2,%3}, [%4];"
                 : "=r"(r[0]), "=r"(r[1]), "=r"(r[2]), "=r"(r[3]) : "r"(addr));
}
__device__ __forceinline__ void mma16816(float c[4], const uint32_t a[4],
                                         uint32_t b0, uint32_t b1) {
    asm volatile(
        "mma.sync.aligned.m16n8k16.row.col.f32.f16.f16.f32 "
        "{%0,%1,%2,%3}, {%4,%5,%6,%7}, {%8,%9}, {%0,%1,%2,%3};"
        : "+f"(c[0]), "+f"(c[1]), "+f"(c[2]), "+f"(c[3])
        : "r"(a[0]), "r"(a[1]), "r"(a[2]), "r"(a[3]), "r"(b0), "r"(b1));
}
__device__ __forceinline__ void cpa16(uint32_t saddr, const void* g) {
    asm volatile("cp.async.cg.shared.global [%0], [%1], 16;" :: "r"(saddr), "l"(g) : "memory");
}
__device__ __forceinline__ void cpa4(uint32_t saddr, const void* g) {
    asm volatile("cp.async.ca.shared.global [%0], [%1], 4;" :: "r"(saddr), "l"(g) : "memory");
}
#define CPA_COMMIT() asm volatile("cp.async.commit_group;" ::: "memory")
#define CPA_WAIT0()  asm volatile("cp.async.wait_group 0;" ::: "memory")

__device__ __forceinline__ float gelu_exact(float y) {
    return 0.5f * y * (1.0f + erff(y * 0.70710678118654752f));
}
__device__ __forceinline__ uint32_t packh2(float a, float b) {
    __half2 h = __floats2half2_rn(a, b);
    return *(uint32_t*)&h;
}
// bilinear sample matching the original up2_kernel's exact fp32 expression order
__device__ __forceinline__ float bil96(const float* p, int iy0, int iy1, float wy,
                                       int ix0, int ix1, float wx) {
    float a = p[iy0 * 96 + ix0], b = p[iy1 * 96 + ix0];
    float c = p[iy0 * 96 + ix1], d = p[iy1 * 96 + ix1];
    float ra = a * (1.f - wy) + b * wy;
    float rb = c * (1.f - wy) + d * wy;
    return ra * (1.f - wx) + rb * wx;
}

// ---------------- fused weight prep: all 5 conv weight sets ----------------
__global__ void prep_all(const float* __restrict__ W_up, const float* __restrict__ W_c2,
                         const float* __restrict__ W_d1, const float* __restrict__ W_d2,
                         const float* __restrict__ W_d3, unsigned char* __restrict__ dst)
{
    int total = CH_TOTAL * 4096;
    for (int idx = blockIdx.x * blockDim.x + threadIdx.x; idx < total;
         idx += gridDim.x * blockDim.x) {
        int chunk = idx >> 12;
        int e = idx & 4095;
        int n = e >> 6, k = e & 63;
        const float* W; int CIN, KK, local;
        if (chunk < 98)       { W = W_up; CIN = 128; KK = 49; local = chunk; }
        else if (chunk < 107) { W = W_c2; CIN = 64;  KK = 9;  local = chunk - 98; }
        else if (chunk < 125) { W = W_d1; CIN = 128; KK = 9;  local = chunk - 107; }
        else if (chunk < 134) { W = W_d2; CIN = 64;  KK = 9;  local = chunk - 125; }
        else                  { W = W_d3; CIN = 64;  KK = 9;  local = chunk - 134; }
        int CG = CIN >> 6;
        int tap = local / CG, cg = local - tap * CG;
        float w = W[((size_t)n * CIN + cg * 64 + k) * KK + tap];
        __half hb = __float2half_rn(w);
        __half lb = __float2half_rn(w - __half2float(hb));
        uint32_t off = (uint32_t)n * 128 + ((((k >> 3) ^ (n & 7))) << 4) + (k & 7) * 2;
        unsigned char* base = dst + (size_t)chunk * 16384;
        *(unsigned short*)(base + off)        = __half_as_ushort(hb);
        *(unsigned short*)(base + 8192 + off) = __half_as_ushort(lb);
    }
}

// ---------------- HMMA implicit-GEMM conv (group-staged weights) ----------------
// TM=8 rows x 32 px per CTA (M=256), 64 out chans; warp tile m64 x n32.
// AMODE 0: input = inA (fp32 NCHW).  AMODE 1: inA * aux(smap).
// AMODE 2: cg0 = bilinear-up2(aux = u), cg1 = inH (fp16 NHWC).
// AMODE 3: input = inH (fp16 NHWC).
// MODE 0: beta*(acc+bias)   MODE 1: gelu(bn(acc+bias))
// OUTF 0: fp32 NCHW (outF)  OUTF 1: fp16 NHWC (outH)
template<int KS, int CG, int G, int MODE, int AMODE, int OUTF>
__global__ __launch_bounds__(256, 2)
void tconv(const float* __restrict__ inA, const __half* __restrict__ inH,
           const float* __restrict__ aux,
           const uint4* __restrict__ wch, const float* __restrict__ bias,
           const float* __restrict__ gg, const float* __restrict__ bb,
           const float* __restrict__ mm, const float* __restrict__ vv,
           const float* __restrict__ betap,
           float* __restrict__ outF, __half* __restrict__ outH,
           int H, int W)
{
    constexpr int PAD = KS / 2;
    constexpr int TM  = 8;
    constexpr int IH  = TM + KS - 1;
    constexpr int IWP = (KS == 3) ? 34 : 40;
    constexpr int NPX = IH * IWP;
    constexpr int KK  = KS * KS;
    constexpr int GPC = (KK + G - 1) / G;
    constexpr int NGRP = GPC * CG;
    constexpr int OFF_A = 1024;
    constexpr int OFF_B = 1024 + NPX * 128;
    constexpr int BSTRIDE = G * 8192;

    extern __shared__ char smem_raw[];
    char* smem = (char*)(((uintptr_t)smem_raw + 1023) & ~(uintptr_t)1023);
    uint32_t sb = smem_u32(smem);
    float* epi = (float*)smem;

    int tid = threadIdx.x, wid = tid >> 5, lane = tid & 31;
    int x0 = blockIdx.x * 32, y0 = blockIdx.y * TM, b = blockIdx.z;
    size_t HW = (size_t)H * W;

    auto stage_group = [&](int fg, int buf) {
        int cgg = fg / GPC, grp = fg - cgg * GPC;
        int t0 = grp * G;
        int cnt = (KK - t0 < G) ? (KK - t0) : G;
        for (int j = 0; j < cnt; j++) {
            int chunk = (t0 + j) * CG + cgg;
            const uint4* srcB = wch + (size_t)chunk * 1024;
            uint32_t dstB = sb + OFF_B + buf * BSTRIDE + j * 8192;
#pragma unroll
            for (int k = 0; k < 2; k++)
                cpa16(dstB + (uint32_t)(tid + k * 256) * 16, srcB + tid + k * 256);
        }
        CPA_COMMIT();
    };

    stage_group(0, 0);

    if (tid < 64) {
        int c = tid;
        float s, t;
        if (MODE == 1) {
            s = gg[c] * rsqrtf(vv[c] + 1e-5f);
            t = (bias[c] - mm[c]) * s + bb[c];
        } else {
            float bt = *betap;
            s = bt; t = bt * bias[c];
        }
        epi[c] = s; epi[64 + c] = t;
    }

    float acc[16][4];
#pragma unroll
    for (int i = 0; i < 16; i++)
#pragma unroll
        for (int j = 0; j < 4; j++) acc[i][j] = 0.f;

    int wm = wid >> 1, nh = wid & 1;
    int ar = lane & 15, akq = lane >> 4;
    int br = lane & 15, bkq = lane >> 4;

    int fg = 0;
    for (int cg = 0; cg < CG; cg++) {
        __syncthreads();

        // ---- stage halo ----
        constexpr int TOT = NPX * 8;
        bool h16 = (AMODE == 3) || (AMODE == 2 && CG == 2);
        if (h16 && (AMODE == 3 || cg == 1)) {
            for (int item = tid; item < TOT; item += 256) {
                int ph = item >> 3, o = item & 7;
                int hy = ph / IWP, hx = ph - hy * IWP;
                int gy = y0 + hy - PAD;
                int gx = x0 + hx - PAD;
                uint4 val = make_uint4(0, 0, 0, 0);
                if ((unsigned)gy < (unsigned)H && (unsigned)gx < (unsigned)W)
                    val = *(const uint4*)(inH + ((((size_t)b * H + gy) * W + gx) << 6) + o * 8);
                uint32_t ad = (uint32_t)ph * 128 + (((o ^ (ph & 7))) << 4);
                *(uint4*)(smem + OFF_A + ad) = val;
            }
        } else {
            const float* src = nullptr;
            if (AMODE != 2) src = inA + ((size_t)b * (CG * 64) + cg * 64) * HW;
            const float rr = 95.f / 191.f;
            for (int item = tid; item < TOT; item += 256) {
                int o  = item / NPX;
                int ph = item - o * NPX;
                int hy = ph / IWP, hx = ph - hy * IWP;
                int gy = y0 + hy - PAD;
                int gx = x0 + hx - PAD;
                float v[8];
                bool inb = (unsigned)gy < (unsigned)H && (unsigned)gx < (unsigned)W;
                if (AMODE == 2) {
                    if (inb) {
                        float sy = gy * rr; int iy0 = (int)sy; float wy = sy - (float)iy0;
                        int iy1 = min(iy0 + 1, 95);
                        float sx = gx * rr; int ix0 = (int)sx; float wx = sx - (float)ix0;
                        int ix1 = min(ix0 + 1, 95);
                        const float* up = aux + (size_t)(b * 64 + o * 8) * 9216;
#pragma unroll
                        for (int j = 0; j < 8; j++)
                            v[j] = bil96(up + j * 9216, iy0, iy1, wy, ix0, ix1, wx);
                    } else {
#pragma unroll
                        for (int j = 0; j < 8; j++) v[j] = 0.f;
                    }
                } else {
                    if (inb) {
                        const float* p = src + (size_t)(o * 8) * HW + (size_t)gy * W + gx;
#pragma unroll
                        for (int j = 0; j < 8; j++) v[j] = p[j * HW];
                        if (AMODE == 1) {
                            float sv = aux[(size_t)b * HW + (size_t)gy * W + gx];
#pragma unroll
                            for (int j = 0; j < 8; j++) v[j] *= sv;
                        }
                    } else {
#pragma unroll
                        for (int j = 0; j < 8; j++) v[j] = 0.f;
                    }
                }
                uint4 hi4;
                hi4.x = packh2(v[0], v[1]); hi4.y = packh2(v[2], v[3]);
                hi4.z = packh2(v[4], v[5]); hi4.w = packh2(v[6], v[7]);
                uint32_t ad = (uint32_t)ph * 128 + (((o ^ (ph & 7))) << 4);
                *(uint4*)(smem + OFF_A + ad) = hi4;
            }
        }

        for (int grp = 0; grp < GPC; grp++, fg++) {
            int s = fg & 1;
            CPA_WAIT0();
            __syncthreads();

            if (fg + 1 < NGRP) stage_group(fg + 1, s ^ 1);

            int t0 = grp * G;
#pragma unroll
            for (int j = 0; j < G; j++) {
                int tap = t0 + j;
                if (tap < KK) {
                    int tapy = tap / KS, tapx = tap - tapy * KS;
                    uint32_t bbase = sb + OFF_B + s * BSTRIDE + j * 8192;
#pragma unroll
                    for (int kc = 0; kc < 4; kc++) {
                        uint32_t a[4][4];
#pragma unroll
                        for (int t = 0; t < 4; t++) {
                            int y = wm * 2 + (t >> 1);
                            int ph = (y + tapy) * IWP + (t & 1) * 16 + ar + tapx;
                            ldm4(sb + OFF_A + (uint32_t)ph * 128
                                 + ((((kc * 2 + akq) ^ (ph & 7))) << 4), a[t]);
                        }
#pragma unroll
                        for (int g = 0; g < 2; g++) {
                            int n = nh * 32 + g * 16 + br;
                            uint32_t ba = bbase + (uint32_t)n * 128
                                        + ((((kc * 2 + bkq) ^ (n & 7))) << 4);
                            uint32_t bh[4];
                            ldm4(ba, bh);
#pragma unroll
                            for (int t = 0; t < 4; t++) {
                                mma16816(acc[t * 4 + 2 * g],     a[t], bh[0], bh[2]);
                                mma16816(acc[t * 4 + 2 * g + 1], a[t], bh[1], bh[3]);
                            }
                        }
                    }
                }
            }
        }
    }

    // ---- epilogue ----
    __syncthreads();
    float* tb = (float*)(smem + 1024);
    {
        int row = lane >> 2, colp = (lane & 3) * 2;
#pragma unroll
        for (int t = 0; t < 4; t++) {
            int p0 = wm * 64 + t * 16 + row;
#pragma unroll
            for (int j = 0; j < 4; j++) {
                int c = nh * 32 + j * 8 + colp;
                tb[p0 * 65 + c]            = acc[t * 4 + j][0];
                tb[p0 * 65 + c + 1]        = acc[t * 4 + j][1];
                tb[(p0 + 8) * 65 + c]      = acc[t * 4 + j][2];
                tb[(p0 + 8) * 65 + c + 1]  = acc[t * 4 + j][3];
            }
        }
    }
    __syncthreads();
    if (OUTF == 0) {
#pragma unroll 4
        for (int it = 0; it < 64; it++) {
            int item = it * 8 + wid;
            int c = item >> 3, py = item & 7;
            float v = tb[(py * 32 + lane) * 65 + c] * epi[c] + epi[64 + c];
            if (MODE == 1) v = gelu_exact(v);
            outF[((size_t)(b * 64 + c) * H + (y0 + py)) * W + x0 + lane] = v;
        }
    } else {
#pragma unroll
        for (int it = 0; it < 8; it++) {
            int item = it * 256 + tid;
            int px = item >> 3, grp = item & 7;
            float vs[8];
#pragma unroll
            for (int j = 0; j < 8; j++) {
                int c = grp * 8 + j;
                float v = tb[px * 65 + c] * epi[c] + epi[64 + c];
                if (MODE == 1) v = gelu_exact(v);
                vs[j] = v;
            }
            uint4 pk;
            pk.x = packh2(vs[0], vs[1]); pk.y = packh2(vs[2], vs[3]);
            pk.z = packh2(vs[4], vs[5]); pk.w = packh2(vs[6], vs[7]);
            int py = px >> 5, xx = px & 31;
            *(uint4*)(outH + ((((size_t)b * H + y0 + py) * W + x0 + xx) << 6) + grp * 8) = pk;
        }
    }
}

// ---------------- AP_MP diff with inline up2(u), 2 outputs/thread ----------------
__global__ void diff_kernel(const float* __restrict__ u, const float* __restrict__ x,
                            float* __restrict__ out)
{
    int idx = blockIdx.x * blockDim.x + threadIdx.x;
    if (idx >= B_ * h_ * (w_ / 2)) return;
    int jp = idx % (w_ / 2);
    int t = idx / (w_ / 2);
    int i = t % h_;
    int b = t / h_;
    int j0 = 2 * jp;
    const float rr = 95.f / 191.f;

    float syA = (2 * i) * rr;     int iyA0 = (int)syA; float wyA = syA - (float)iyA0; int iyA1 = min(iyA0 + 1, 95);
    float syB = (2 * i + 1) * rr; int iyB0 = (int)syB; float wyB = syB - (float)iyB0; int iyB1 = min(iyB0 + 1, 95);

    float sxA0 = (2 * j0) * rr;     int ixA00 = (int)sxA0; float wxA0 = sxA0 - (float)ixA00; int ixA01 = min(ixA00 + 1, 95);
    float sxB0 = (2 * j0 + 1) * rr; int ixB00 = (int)sxB0; float wxB0 = sxB0 - (float)ixB00; int ixB01 = min(ixB00 + 1, 95);
    float sxA1 = (2 * j0 + 2) * rr; int ixA10 = (int)sxA1; float wxA1 = sxA1 - (float)ixA10; int ixA11 = min(ixA10 + 1, 95);
    float sxB1 = (2 * j0 + 3) * rr; int ixB10 = (int)sxB1; float wxB1 = sxB1 - (float)ixB10; int ixB11 = min(ixB10 + 1, 95);

    float a1_0 = 0.f, a2_0 = 0.f, a1_1 = 0.f, a2_1 = 0.f;
    size_t base0 = ((size_t)b * 64 * H_ + 2 * i) * W_ + 4 * jp;
    for (int c = 0; c < 64; c++) {
        const float* uc = u + (size_t)(b * 64 + c) * 9216;
        size_t base = base0 + (size_t)c * H_ * W_;
        float4 xr0 = *(const float4*)(x + base);
        float4 xr1 = *(const float4*)(x + base + W_);

        {
            float s00 = bil96(uc, iyA0, iyA1, wyA, ixA00, ixA01, wxA0);
            float s01 = bil96(uc, iyA0, iyA1, wyA, ixB00, ixB01, wxB0);
            float s10 = bil96(uc, iyB0, iyB1, wyB, ixA00, ixA01, wxA0);
            float s11 = bil96(uc, iyB0, iyB1, wyB, ixB00, ixB01, wxB0);
            float as = 0.25f * (s00 + s01 + s10 + s11);
            float ms = fmaxf(fmaxf(s00, s01), fmaxf(s10, s11));
            float ax = 0.25f * (xr0.x + xr0.y + xr1.x + xr1.y);
            float mx = fmaxf(fmaxf(xr0.x, xr0.y), fmaxf(xr1.x, xr1.y));
            float d1 = as - mx; a1_0 += d1 * d1;
            float d2 = ax - ms; a2_0 += d2 * d2;
        }
        {
            float s00 = bil96(uc, iyA0, iyA1, wyA, ixA10, ixA11, wxA1);
            float s01 = bil96(uc, iyA0, iyA1, wyA, ixB10, ixB11, wxB1);
            float s10 = bil96(uc, iyB0, iyB1, wyB, ixA10, ixA11, wxA1);
            float s11 = bil96(uc, iyB0, iyB1, wyB, ixB10, ixB11, wxB1);
            float as = 0.25f * (s00 + s01 + s10 + s11);
            float ms = fmaxf(fmaxf(s00, s01), fmaxf(s10, s11));
            float ax = 0.25f * (xr0.z + xr0.w + xr1.z + xr1.w);
            float mx = fmaxf(fmaxf(xr0.z, xr0.w), fmaxf(xr1.z, xr1.w));
            float d1 = as - mx; a1_1 += d1 * d1;
            float d2 = ax - ms; a2_1 += d2 * d2;
        }
    }
    size_t ob = ((size_t)b * h_ + i) * w_ + j0;
    out[ob]     = sqrtf(a1_0) + sqrtf(a2_0);
    out[ob + 1] = sqrtf(a1_1) + sqrtf(a2_1);
}

// ---------------- smap: sigmoid(up2(map)) x2 -> (dilate3-map)x2 + 1 ----------------
__global__ __launch_bounds__(256)
void smap_kernel(const float* __restrict__ in_map, const float* __restrict__ ds,
                 float* __restrict__ smap)
{
    __shared__ float s_i[10 * 34];
    __shared__ float s_d[10 * 34];
    int tid = threadIdx.x;
    int x0 = blockIdx.x * 32, y0 = blockIdx.y * 8, b = blockIdx.z;
    const float rr = 95.f / 191.f;
    const float* pi = in_map + (size_t)b * h_ * w_;
    const float* pd = ds + (size_t)b * h_ * w_;

    for (int item = tid; item < 340; item += 256) {
        int hy = item / 34, hx = item - hy * 34;
        int gy = y0 - 1 + hy, gx = x0 - 1 + hx;
        float vi = -INFINITY, vd = -INFINITY;
        if ((unsigned)gy < (unsigned)H_ && (unsigned)gx < (unsigned)W_) {
            float sy = gy * rr; int iy0 = (int)sy; float wy = sy - (float)iy0;
            int iy1 = min(iy0 + 1, h_ - 1);
            float sx = gx * rr; int ix0 = (int)sx; float wx = sx - (float)ix0;
            int ix1 = min(ix0 + 1, w_ - 1);
            float w00 = (1.f - wy) * (1.f - wx), w01 = (1.f - wy) * wx;
            float w10 = wy * (1.f - wx),         w11 = wy * wx;
            float ui = pi[iy0 * w_ + ix0] * w00 + pi[iy0 * w_ + ix1] * w01
                     + pi[iy1 * w_ + ix0] * w10 + pi[iy1 * w_ + ix1] * w11;
            float ud = pd[iy0 * w_ + ix0] * w00 + pd[iy0 * w_ + ix1] * w01
                     + pd[iy1 * w_ + ix0] * w10 + pd[iy1 * w_ + ix1] * w11;
            vi = 1.f / (1.f + expf(-ui));
            vd = 1.f / (1.f + expf(-ud));
        }
        s_i[item] = vi; s_d[item] = vd;
    }
    __syncthreads();

    int tx = tid & 31, ty = tid >> 5;
    int ci = (ty + 1) * 34 + tx + 1;
    float mi = -INFINITY, md = -INFINITY;
#pragma unroll
    for (int dy = 0; dy < 3; dy++)
#pragma unroll
        for (int dx = 0; dx < 3; dx++) {
            int o = (ty + dy) * 34 + tx + dx;
            mi = fmaxf(mi, s_i[o]);
            md = fmaxf(md, s_d[o]);
        }
    float s = (mi - s_i[ci]) + (md - s_d[ci]) + 1.0f;
    smap[((size_t)b * H_ + (y0 + ty)) * W_ + x0 + tx] = s;
}

// ---------------- final conv 7x7, 64 -> 1 (fp32), 4 consecutive px/thread ----------------
// Weight smem padded to stride 8 per ky row -> vectorized weight loads.
// Accumulation order (c, ky, kx) per output unchanged -> bit-identical.
__global__ __launch_bounds__(256)
void conv_out_kernel(const float* __restrict__ rin, const float* __restrict__ Wo,
                     const float* __restrict__ bo, float* __restrict__ out)
{
    extern __shared__ float s_dyn[];           // 2 x (8*22*70)
    __shared__ float s_w[64 * 56];             // [c][ky*8 + kx], kx7 padded to 8
    constexpr int BUFE = 8 * 22 * 70;          // 12320 floats
    uint32_t sdb = smem_u32(s_dyn);

    int tid = threadIdx.x;
    int tx4 = tid & 15, ty = tid >> 4;         // 16 x-groups x 16 rows
    int x0 = blockIdx.x * 64, ys = blockIdx.y * 16, b = blockIdx.z;

    for (int idx = tid; idx < 64 * 49; idx += 256) {
        int c = idx / 49, r = idx - c * 49;
        int ky = r / 7, kx = r - ky * 7;
        s_w[c * 56 + ky * 8 + kx] = Wo[idx];
    }

    auto stage = [&](int c0, int buf) {
        float* dst = s_dyn + buf * BUFE;
        uint32_t dbase = sdb + (uint32_t)buf * BUFE * 4;
        for (int idx = tid; idx < BUFE; idx += 256) {
            int c = idx / (22 * 70);
            int r = idx - c * (22 * 70);
            int ly = r / 70, lx = r - ly * 70;
            int gy = ys + ly - 3, gx = x0 + lx - 3;
            if ((unsigned)gy < (unsigned)H_ && (unsigned)gx < (unsigned)W_)
                cpa4(dbase + (uint32_t)idx * 4,
                     rin + ((size_t)(b * 64 + c0 + c) * H_ + gy) * W_ + gx);
            else
                dst[idx] = 0.f;
        }
        CPA_COMMIT();
    };

    stage(0, 0);
    CPA_WAIT0();
    __syncthreads();

    float a0 = 0.f, a1 = 0.f, a2 = 0.f, a3 = 0.f;
    for (int it = 0; it < 8; it++) {
        int buf = it & 1;
        if (it + 1 < 8) stage((it + 1) * 8, buf ^ 1);
        const float* cur = s_dyn + buf * BUFE;
#pragma unroll
        for (int c = 0; c < 8; c++) {
            const float* wrow = &s_w[(it * 8 + c) * 56];
#pragma unroll
            for (int ky = 0; ky < 7; ky++) {
                const float* row = cur + (c * 22 + ty + ky) * 70 + 4 * tx4;
                // 10-value window via 5 aligned float2 loads
                float2 p0 = *(const float2*)(row + 0);
                float2 p1 = *(const float2*)(row + 2);
                float2 p2 = *(const float2*)(row + 4);
                float2 p3 = *(const float2*)(row + 6);
                float2 p4 = *(const float2*)(row + 8);
                float in[10] = { p0.x, p0.y, p1.x, p1.y, p2.x, p2.y,
                                 p3.x, p3.y, p4.x, p4.y };
                float2 w01 = *(const float2*)(wrow + ky * 8);
                float2 w23 = *(const float2*)(wrow + ky * 8 + 2);
                float2 w45 = *(const float2*)(wrow + ky * 8 + 4);
                float w6   = wrow[ky * 8 + 6];
                float wv[7] = { w01.x, w01.y, w23.x, w23.y, w45.x, w45.y, w6 };
#pragma unroll
                for (int kx = 0; kx < 7; kx++) {
                    float w = wv[kx];
                    a0 += w * in[kx];
                    a1 += w * in[kx + 1];
                    a2 += w * in[kx + 2];
                    a3 += w * in[kx + 3];
                }
            }
        }
        CPA_WAIT0();
        __syncthreads();
    }
    float bv = bo[0];
    float4 res = make_float4(a0 + bv, a1 + bv, a2 + bv, a3 + bv);
    *(float4*)(out + ((size_t)b * H_ + (ys + ty)) * W_ + x0 + 4 * tx4) = res;
}

// ---------------- launch ----------------
#define SMEM_UP (1024 + 14*40*128 + 2*2*8192)   // 105472  (KS=7, G=2)
#define SMEM_3  (1024 + 10*34*128 + 2*3*8192)   // 93696   (KS=3, G=3)
#define SMEM_CO (2*8*22*70*4)                   // 98560

extern "C" void kernel_launch(void* const* d_in, const int* in_sizes, int n_in,
                              void* d_out, int out_size)
{
    const float* x       = (const float*)d_in[0];
    const float* small_x = (const float*)d_in[1];
    const float* in_map  = (const float*)d_in[2];
    const float* W_up  = (const float*)d_in[3];
    const float* b_up  = (const float*)d_in[4];
    const float* gup   = (const float*)d_in[5];
    const float* beup  = (const float*)d_in[6];
    const float* mup   = (const float*)d_in[7];
    const float* vup   = (const float*)d_in[8];
    const float* W_c2  = (const float*)d_in[9];
    const float* b_c2  = (const float*)d_in[10];
    const float* W_d1  = (const float*)d_in[11];
    const float* b_d1  = (const float*)d_in[12];
    const float* gd1   = (const float*)d_in[13];
    const float* bed1  = (const float*)d_in[14];
    const float* md1   = (const float*)d_in[15];
    const float* vd1   = (const float*)d_in[16];
    const float* W_d2  = (const float*)d_in[17];
    const float* b_d2  = (const float*)d_in[18];
    const float* gd2   = (const float*)d_in[19];
    const float* bed2  = (const float*)d_in[20];
    const float* md2   = (const float*)d_in[21];
    const float* vd2   = (const float*)d_in[22];
    const float* W_d3  = (const float*)d_in[23];
    const float* b_d3  = (const float*)d_in[24];
    const float* gd3   = (const float*)d_in[25];
    const float* bed3  = (const float*)d_in[26];
    const float* md3   = (const float*)d_in[27];
    const float* vd3   = (const float*)d_in[28];
    const float* W_out = (const float*)d_in[29];
    const float* b_out = (const float*)d_in[30];
    const float* beta  = (const float*)d_in[31];

    float *u, *ds, *sp;
    __half *fn16, *r116, *r216;
    unsigned char* wbf;
    cudaGetSymbolAddress((void**)&u,    g_u);
    cudaGetSymbolAddress((void**)&ds,   g_diffs);
    cudaGetSymbolAddress((void**)&sp,   g_smap);
    cudaGetSymbolAddress((void**)&fn16, g_fn16);
    cudaGetSymbolAddress((void**)&r116, g_r116);
    cudaGetSymbolAddress((void**)&r216, g_r216);
    cudaGetSymbolAddress((void**)&wbf,  g_wbf);

    cudaFuncSetAttribute(tconv<7,2,2,1,0,0>, cudaFuncAttributeMaxDynamicSharedMemorySize, SMEM_UP);
    cudaFuncSetAttribute(tconv<3,1,3,0,1,1>, cudaFuncAttributeMaxDynamicSharedMemorySize, SMEM_3);
    cudaFuncSetAttribute(tconv<3,2,3,1,2,1>, cudaFuncAttributeMaxDynamicSharedMemorySize, SMEM_3);
    cudaFuncSetAttribute(tconv<3,1,3,1,3,1>, cudaFuncAttributeMaxDynamicSharedMemorySize, SMEM_3);
    cudaFuncSetAttribute(tconv<3,1,3,1,3,0>, cudaFuncAttributeMaxDynamicSharedMemorySize, SMEM_3);
    cudaFuncSetAttribute(conv_out_kernel,    cudaFuncAttributeMaxDynamicSharedMemorySize, SMEM_CO);

    // 1) fused weight prep
    prep_all<<<1024, 256>>>(W_up, W_c2, W_d1, W_d2, W_d3, wbf);

    // 2) up branch: conv7x7 + BN + GELU -> u (96x96 fp32)
    tconv<7,2,2,1,0,0><<<dim3(3, 12, 8), 256, SMEM_UP>>>(
        small_x, nullptr, nullptr, (const uint4*)(wbf + (size_t)CH_UP * 16384),
        b_up, gup, beup, mup, vup, nullptr, u, nullptr, h_, w_);

    // 3) uncertainty maps
    diff_kernel<<<(B_ * h_ * (w_ / 2) + 255) / 256, 256>>>(u, x, ds);
    smap_kernel<<<dim3(6, 24, 8), 256>>>(in_map, ds, sp);

    // 4) conv chain (HMMA fp16; inter-layer buffers fp16 NHWC)
    tconv<3,1,3,0,1,1><<<dim3(6, 24, 8), 256, SMEM_3>>>(
        x, nullptr, sp, (const uint4*)(wbf + (size_t)CH_C2 * 16384),
        b_c2, nullptr, nullptr, nullptr, nullptr, beta, nullptr, fn16, H_, W_);
    tconv<3,2,3,1,2,1><<<dim3(6, 24, 8), 256, SMEM_3>>>(
        nullptr, fn16, u, (const uint4*)(wbf + (size_t)CH_D1 * 16384),
        b_d1, gd1, bed1, md1, vd1, nullptr, nullptr, r116, H_, W_);
    tconv<3,1,3,1,3,1><<<dim3(6, 24, 8), 256, SMEM_3>>>(
        nullptr, r116, nullptr, (const uint4*)(wbf + (size_t)CH_D2 * 16384),
        b_d2, gd2, bed2, md2, vd2, nullptr, nullptr, r216, H_, W_);
    tconv<3,1,3,1,3,0><<<dim3(6, 24, 8), 256, SMEM_3>>>(
        nullptr, r216, nullptr, (const uint4*)(wbf + (size_t)CH_D3 * 16384),
        b_d3, gd3, bed3, md3, vd3, nullptr, (float*)d_out, nullptr, H_, W_);

    // 5) output head (reads r from d_out, writes output_map after it)
    conv_out_kernel<<<dim3(3, 12, 8), 256, SMEM_CO>>>(
        (const float*)d_out, W_out, b_out, (float*)d_out + R_ELEMS);
}